// round 2
// baseline (speedup 1.0000x reference)
#include <cuda_runtime.h>
#include <math.h>

#define TILE_M 128
#define THREADS 256
#define SA_STRIDE 132   // 128 + 4 pad -> conflict-free A-fragment loads
#define SB_STRIDE 136   // 128 + 8 pad -> conflict-free B-fragment loads

// smem layout (floats): sA[128*132] | sB[128*136] | sIdx[256 ints] | sW4[128]
#define SMEM_FLOATS (TILE_M*SA_STRIDE + 128*SB_STRIDE)
#define SMEM_BYTES  (SMEM_FLOATS*4 + 256*4 + 128*4)

__device__ __forceinline__ unsigned tf32r(float f) {
    unsigned u;
    asm("cvt.rna.tf32.f32 %0, %1;" : "=r"(u) : "f"(f));
    return u;
}

__device__ __forceinline__ void mma_tf32(float* c,
    unsigned a0, unsigned a1, unsigned a2, unsigned a3,
    unsigned b0, unsigned b1)
{
    asm volatile(
        "mma.sync.aligned.m16n8k8.row.col.f32.tf32.tf32.f32 "
        "{%0,%1,%2,%3},{%4,%5,%6,%7},{%8,%9},{%0,%1,%2,%3};"
        : "+f"(c[0]), "+f"(c[1]), "+f"(c[2]), "+f"(c[3])
        : "r"(a0), "r"(a1), "r"(a2), "r"(a3), "r"(b0), "r"(b1));
}

__global__ void __launch_bounds__(THREADS, 1)
edgepred_fused_kernel(
    const float* __restrict__ x,
    const int* __restrict__ ei,          // edge_index is int32 on device (JAX x64 disabled)
    const float* __restrict__ W1, const float* __restrict__ b1,
    const float* __restrict__ W2, const float* __restrict__ b2,
    const float* __restrict__ W3, const float* __restrict__ b3,
    const float* __restrict__ W4, const float* __restrict__ b4,
    float* __restrict__ out, int E, int N)
{
    extern __shared__ float smem[];
    float* sA   = smem;                          // 128 x SA_STRIDE
    float* sB   = sA + TILE_M * SA_STRIDE;       // 128 x SB_STRIDE
    int*   sIdx = (int*)(sB + 128 * SB_STRIDE);  // 256: [0..127]=src, [128..255]=dst
    float* sW4  = (float*)(sIdx + 256);          // 128

    const int tid    = threadIdx.x;
    const int lane   = tid & 31;
    const int wid    = tid >> 5;
    const int warp_m = wid >> 2;   // 0..1 -> rows [warp_m*64, +64)
    const int warp_n = wid & 3;    // 0..3 -> cols [warp_n*32, +32)
    const int qid    = lane >> 2;  // groupID
    const int tig    = lane & 3;   // thread-in-group
    const long long tile0 = (long long)blockIdx.x * TILE_M;

    // ---- load edge indices (src / dst), clamped defensively ----
    {
        int half = (tid < 128) ? 0 : 1;
        int r    = tid & 127;
        long long e = tile0 + r;
        int idx = 0;
        if (e < E) idx = ei[(long long)half * E + e];
        if (idx < 0)  idx = 0;
        if (idx >= N) idx = N - 1;
        sIdx[half * 128 + r] = idx;
    }
    __syncthreads();

    // ---- cooperative loaders (2 threads per row, 64 floats each) ----
    const int lrow  = tid >> 1;
    const int lhalf = (tid & 1) * 64;

    auto load_act = [&](const int* idxs) {
        const float4* xr = (const float4*)(x + (long long)idxs[lrow] * 128 + lhalf);
        float* dst = sA + lrow * SA_STRIDE + lhalf;
        #pragma unroll
        for (int i = 0; i < 16; ++i) {
            float4 v = xr[i];
            float4 o;
            o.x = __uint_as_float(tf32r(v.x));
            o.y = __uint_as_float(tf32r(v.y));
            o.z = __uint_as_float(tf32r(v.z));
            o.w = __uint_as_float(tf32r(v.w));
            *(float4*)(dst + i * 4) = o;
        }
    };
    auto load_w = [&](const float* W) {
        const float4* wr = (const float4*)(W + lrow * 128 + lhalf);
        float* dst = sB + lrow * SB_STRIDE + lhalf;
        #pragma unroll
        for (int i = 0; i < 16; ++i) {
            float4 v = wr[i];
            float4 o;
            o.x = __uint_as_float(tf32r(v.x));
            o.y = __uint_as_float(tf32r(v.y));
            o.z = __uint_as_float(tf32r(v.z));
            o.w = __uint_as_float(tf32r(v.w));
            *(float4*)(dst + i * 4) = o;
        }
    };

    float acc[4][4][4];  // [mt][nt][4]
    auto zero_acc = [&]() {
        #pragma unroll
        for (int mt = 0; mt < 4; ++mt)
            #pragma unroll
            for (int nt = 0; nt < 4; ++nt)
                #pragma unroll
                for (int i = 0; i < 4; ++i) acc[mt][nt][i] = 0.f;
    };

    // GEMM over current sA (128 x 128) @ sB (128 x 128) accumulating into acc
    auto run_mma = [&]() {
        for (int kt = 0; kt < 16; ++kt) {
            const int kb = kt * 8;
            unsigned b0r[4], b1r[4];
            #pragma unroll
            for (int nt = 0; nt < 4; ++nt) {
                int colb = warp_n * 32 + nt * 8 + qid;
                b0r[nt] = __float_as_uint(sB[(kb + tig)     * SB_STRIDE + colb]);
                b1r[nt] = __float_as_uint(sB[(kb + 4 + tig) * SB_STRIDE + colb]);
            }
            #pragma unroll
            for (int mt = 0; mt < 4; ++mt) {
                int rowa = warp_m * 64 + mt * 16 + qid;
                const float* pa = sA + rowa * SA_STRIDE + kb + tig;
                unsigned a0 = __float_as_uint(pa[0]);
                unsigned a2 = __float_as_uint(pa[4]);
                unsigned a1 = __float_as_uint(pa[8 * SA_STRIDE]);
                unsigned a3 = __float_as_uint(pa[8 * SA_STRIDE + 4]);
                #pragma unroll
                for (int nt = 0; nt < 4; ++nt)
                    mma_tf32(acc[mt][nt], a0, a1, a2, a3, b0r[nt], b1r[nt]);
            }
        }
    };

    // bias + relu, write activations back to sA (optionally tf32-rounded)
    auto epilogue = [&](const float* __restrict__ bias, bool roundNext) {
        #pragma unroll
        for (int mt = 0; mt < 4; ++mt) {
            int row = warp_m * 64 + mt * 16 + qid;
            #pragma unroll
            for (int nt = 0; nt < 4; ++nt) {
                int col = warp_n * 32 + nt * 8 + 2 * tig;
                float bb0 = __ldg(&bias[col]);
                float bb1 = __ldg(&bias[col + 1]);
                float v0 = fmaxf(acc[mt][nt][0] + bb0, 0.f);
                float v1 = fmaxf(acc[mt][nt][1] + bb1, 0.f);
                float v2 = fmaxf(acc[mt][nt][2] + bb0, 0.f);
                float v3 = fmaxf(acc[mt][nt][3] + bb1, 0.f);
                if (roundNext) {
                    v0 = __uint_as_float(tf32r(v0));
                    v1 = __uint_as_float(tf32r(v1));
                    v2 = __uint_as_float(tf32r(v2));
                    v3 = __uint_as_float(tf32r(v3));
                }
                sA[row * SA_STRIDE + col]           = v0;
                sA[row * SA_STRIDE + col + 1]       = v1;
                sA[(row + 8) * SA_STRIDE + col]     = v2;
                sA[(row + 8) * SA_STRIDE + col + 1] = v3;
            }
        }
    };

    // ======== Layer 1, pass A: x_i @ W1[0:128] ========
    load_act(sIdx);          // src rows
    load_w(W1);              // W1 rows 0..127
    __syncthreads();
    zero_acc();
    run_mma();
    __syncthreads();

    // ======== Layer 1, pass B: + x_j @ W1[128:256] ========
    load_act(sIdx + 128);    // dst rows
    load_w(W1 + 128 * 128);  // W1 rows 128..255
    __syncthreads();
    run_mma();
    __syncthreads();
    epilogue(b1, true);
    load_w(W2);
    __syncthreads();

    // ======== Layer 2 ========
    zero_acc();
    run_mma();
    __syncthreads();
    epilogue(b2, true);
    load_w(W3);
    __syncthreads();

    // ======== Layer 3 ========
    zero_acc();
    run_mma();
    __syncthreads();
    epilogue(b3, false);     // keep fp32 for final dot
    if (tid < 128) sW4[tid] = W4[tid];
    __syncthreads();

    // ======== Layer 4: dot + sigmoid ========
    if (tid < 128) {
        long long e = tile0 + tid;
        if (e < E) {
            float z = __ldg(b4);
            const float* hr = sA + tid * SA_STRIDE;
            #pragma unroll
            for (int j = 0; j < 128; j += 4) {
                z += hr[j]     * sW4[j]
                   + hr[j + 1] * sW4[j + 1]
                   + hr[j + 2] * sW4[j + 2]
                   + hr[j + 3] * sW4[j + 3];
            }
            out[e] = 1.f / (1.f + expf(-z));
        }
    }
}

extern "C" void kernel_launch(void* const* d_in, const int* in_sizes, int n_in,
                              void* d_out, int out_size)
{
    const float* x  = (const float*)d_in[0];
    const int*   ei = (const int*)d_in[1];      // int32 (JAX default: x64 disabled)
    const float* W1 = (const float*)d_in[2];
    const float* b1 = (const float*)d_in[3];
    const float* W2 = (const float*)d_in[4];
    const float* b2 = (const float*)d_in[5];
    const float* W3 = (const float*)d_in[6];
    const float* b3 = (const float*)d_in[7];
    const float* W4 = (const float*)d_in[8];
    const float* b4 = (const float*)d_in[9];
    float* out = (float*)d_out;

    int E = in_sizes[1] / 2;    // edge_index is (2, E)
    int N = in_sizes[0] / 128;  // x is (N, 128)
    int nTiles = (E + TILE_M - 1) / TILE_M;

    cudaFuncSetAttribute(edgepred_fused_kernel,
                         cudaFuncAttributeMaxDynamicSharedMemorySize, SMEM_BYTES);

    edgepred_fused_kernel<<<nTiles, THREADS, SMEM_BYTES>>>(
        x, ei, W1, b1, W2, b2, W3, b3, W4, b4, out, E, N);
}

// round 3
// speedup vs baseline: 1.5174x; 1.5174x over previous
#include <cuda_runtime.h>
#include <cuda_bf16.h>
#include <math.h>

#define TILE_M 128
#define THREADS 256
#define SAB 136   // bf16 elements per smem row (272B) -> conflict-free LDSM

// smem: sA[128*SAB bf16] | sB[128*SAB bf16] | sIdx[256 int] | sW4[128 float]
#define SMEM_BYTES (2*128*SAB*2 + 256*4 + 128*4)

__device__ __forceinline__ void ldsm_x4(unsigned* r, unsigned addr) {
    asm volatile("ldmatrix.sync.aligned.m8n8.x4.shared.b16 {%0,%1,%2,%3}, [%4];"
        : "=r"(r[0]), "=r"(r[1]), "=r"(r[2]), "=r"(r[3]) : "r"(addr));
}
__device__ __forceinline__ void ldsm_x4_t(unsigned* r, unsigned addr) {
    asm volatile("ldmatrix.sync.aligned.m8n8.x4.trans.shared.b16 {%0,%1,%2,%3}, [%4];"
        : "=r"(r[0]), "=r"(r[1]), "=r"(r[2]), "=r"(r[3]) : "r"(addr));
}
__device__ __forceinline__ void mma_bf16(float* c, const unsigned* a, const unsigned* b) {
    asm volatile(
        "mma.sync.aligned.m16n8k16.row.col.f32.bf16.bf16.f32 "
        "{%0,%1,%2,%3},{%4,%5,%6,%7},{%8,%9},{%0,%1,%2,%3};"
        : "+f"(c[0]), "+f"(c[1]), "+f"(c[2]), "+f"(c[3])
        : "r"(a[0]), "r"(a[1]), "r"(a[2]), "r"(a[3]), "r"(b[0]), "r"(b[1]));
}

__global__ void __launch_bounds__(THREADS, 2)
edgepred_bf16_kernel(
    const float* __restrict__ x,
    const int* __restrict__ ei,
    const float* __restrict__ W1, const float* __restrict__ b1,
    const float* __restrict__ W2, const float* __restrict__ b2,
    const float* __restrict__ W3, const float* __restrict__ b3,
    const float* __restrict__ W4, const float* __restrict__ b4,
    float* __restrict__ out, int E, int N)
{
    extern __shared__ char smem_raw[];
    __nv_bfloat16* sA = (__nv_bfloat16*)smem_raw;            // 128 x SAB
    __nv_bfloat16* sB = sA + 128 * SAB;                      // 128 x SAB
    int*   sIdx = (int*)(sB + 128 * SAB);                    // 256
    float* sW4  = (float*)(sIdx + 256);                      // 128

    const int tid    = threadIdx.x;
    const int lane   = tid & 31;
    const int wid    = tid >> 5;
    const int warp_m = wid >> 2;   // 0..1 -> rows [warp_m*64, +64)
    const int warp_n = wid & 3;    // 0..3 -> cols [warp_n*32, +32)
    const int qid    = lane >> 2;
    const int tig    = lane & 3;
    const long long tile0 = (long long)blockIdx.x * TILE_M;

    const unsigned sA_u = (unsigned)__cvta_generic_to_shared(sA);
    const unsigned sB_u = (unsigned)__cvta_generic_to_shared(sB);

    // ---- edge indices (src / dst), clamped ----
    {
        int half = (tid < 128) ? 0 : 1;
        int r    = tid & 127;
        long long e = tile0 + r;
        int idx = 0;
        if (e < E) idx = ei[(long long)half * E + e];
        if (idx < 0)  idx = 0;
        if (idx >= N) idx = N - 1;
        sIdx[half * 128 + r] = idx;
    }
    __syncthreads();

    // ---- cooperative loaders: 2 threads/row, 64 fp32 -> 64 bf16 each ----
    const int lrow  = tid >> 1;
    const int lhalf = (tid & 1) * 64;

    auto cvt_store = [&](const float4* src, __nv_bfloat16* dstRow) {
        uint4* dst = (uint4*)(dstRow);  // 16B-aligned (row stride 272B, half off 128B)
        #pragma unroll
        for (int i = 0; i < 8; ++i) {
            float4 v0 = src[2 * i];
            float4 v1 = src[2 * i + 1];
            __nv_bfloat162 p0 = __floats2bfloat162_rn(v0.x, v0.y);
            __nv_bfloat162 p1 = __floats2bfloat162_rn(v0.z, v0.w);
            __nv_bfloat162 p2 = __floats2bfloat162_rn(v1.x, v1.y);
            __nv_bfloat162 p3 = __floats2bfloat162_rn(v1.z, v1.w);
            uint4 o;
            o.x = *(unsigned*)&p0; o.y = *(unsigned*)&p1;
            o.z = *(unsigned*)&p2; o.w = *(unsigned*)&p3;
            dst[i] = o;
        }
    };
    auto load_act = [&](const int* idxs) {
        const float4* xr = (const float4*)(x + (long long)idxs[lrow] * 128 + lhalf);
        cvt_store(xr, sA + lrow * SAB + lhalf);
    };
    auto load_w = [&](const float* W) {
        const float4* wr = (const float4*)(W + lrow * 128 + lhalf);
        cvt_store(wr, sB + lrow * SAB + lhalf);
    };

    // ---- per-lane LDSM base addresses ----
    const int sub = lane >> 3;          // which 8x8 matrix this lane addresses
    const int r8  = lane & 7;
    // A tile (mt,kt): row = mt*16 + (sub&1)*8 + r8 ; colblk = kt*16 + (sub>>1)*8
    const unsigned aBase = sA_u + (((sub & 1) * 8 + r8) * SAB + (sub >> 1) * 8) * 2;
    // B tile (kt,ntp): krow = kt*16 + (sub&1)*8 + r8 ; ncol = warp_n*32 + ntp*16 + (sub>>1)*8
    const unsigned bBase = sB_u + (((sub & 1) * 8 + r8) * SAB + warp_n * 32 + (sub >> 1) * 8) * 2;

    float acc[4][4][4];
    auto zero_acc = [&]() {
        #pragma unroll
        for (int mt = 0; mt < 4; ++mt)
            #pragma unroll
            for (int nt = 0; nt < 4; ++nt)
                #pragma unroll
                for (int i = 0; i < 4; ++i) acc[mt][nt][i] = 0.f;
    };

    // 128x128x128 GEMM pass: sA @ sB -> acc
    auto run_mma = [&]() {
        #pragma unroll
        for (int kt = 0; kt < 8; ++kt) {
            unsigned a[4][4], b[2][4];
            #pragma unroll
            for (int mt = 0; mt < 4; ++mt)
                ldsm_x4(a[mt], aBase + (unsigned)((warp_m * 64 + mt * 16) * SAB + kt * 16) * 2);
            #pragma unroll
            for (int ntp = 0; ntp < 2; ++ntp)
                ldsm_x4_t(b[ntp], bBase + (unsigned)(kt * 16 * SAB + ntp * 16) * 2);
            #pragma unroll
            for (int mt = 0; mt < 4; ++mt)
                #pragma unroll
                for (int nt = 0; nt < 4; ++nt)
                    mma_bf16(acc[mt][nt], a[mt], &b[nt >> 1][(nt & 1) * 2]);
        }
    };

    // bias + relu -> bf16 back into sA
    auto epilogue = [&](const float* __restrict__ bias) {
        #pragma unroll
        for (int mt = 0; mt < 4; ++mt) {
            int row = warp_m * 64 + mt * 16 + qid;
            #pragma unroll
            for (int nt = 0; nt < 4; ++nt) {
                int col = warp_n * 32 + nt * 8 + 2 * tig;
                float bb0 = __ldg(&bias[col]);
                float bb1 = __ldg(&bias[col + 1]);
                float v0 = fmaxf(acc[mt][nt][0] + bb0, 0.f);
                float v1 = fmaxf(acc[mt][nt][1] + bb1, 0.f);
                float v2 = fmaxf(acc[mt][nt][2] + bb0, 0.f);
                float v3 = fmaxf(acc[mt][nt][3] + bb1, 0.f);
                *(__nv_bfloat162*)(sA + row * SAB + col)       = __floats2bfloat162_rn(v0, v1);
                *(__nv_bfloat162*)(sA + (row + 8) * SAB + col) = __floats2bfloat162_rn(v2, v3);
            }
        }
    };

    // ======== Layer 1, pass A: x_i @ W1[0:128] ========
    load_act(sIdx);
    load_w(W1);
    __syncthreads();
    zero_acc();
    run_mma();
    __syncthreads();

    // ======== Layer 1, pass B: + x_j @ W1[128:256] ========
    load_act(sIdx + 128);
    load_w(W1 + 128 * 128);
    __syncthreads();
    run_mma();
    __syncthreads();
    epilogue(b1);
    load_w(W2);
    __syncthreads();

    // ======== Layer 2 ========
    zero_acc();
    run_mma();
    __syncthreads();
    epilogue(b2);
    load_w(W3);
    __syncthreads();

    // ======== Layer 3 ========
    zero_acc();
    run_mma();
    __syncthreads();
    epilogue(b3);
    if (tid < 128) sW4[tid] = W4[tid];
    __syncthreads();

    // ======== Layer 4: dot(h3, W4) + sigmoid ========
    if (tid < 128) {
        long long e = tile0 + tid;
        if (e < E) {
            float z = __ldg(b4);
            const __nv_bfloat162* hr = (const __nv_bfloat162*)(sA + tid * SAB);
            #pragma unroll
            for (int j = 0; j < 64; ++j) {
                float2 h2 = __bfloat1622float2(hr[j]);
                z += h2.x * sW4[2 * j] + h2.y * sW4[2 * j + 1];
            }
            out[e] = 1.f / (1.f + expf(-z));
        }
    }
}

extern "C" void kernel_launch(void* const* d_in, const int* in_sizes, int n_in,
                              void* d_out, int out_size)
{
    const float* x  = (const float*)d_in[0];
    const int*   ei = (const int*)d_in[1];
    const float* W1 = (const float*)d_in[2];
    const float* b1 = (const float*)d_in[3];
    const float* W2 = (const float*)d_in[4];
    const float* b2 = (const float*)d_in[5];
    const float* W3 = (const float*)d_in[6];
    const float* b3 = (const float*)d_in[7];
    const float* W4 = (const float*)d_in[8];
    const float* b4 = (const float*)d_in[9];
    float* out = (float*)d_out;

    int E = in_sizes[1] / 2;    // edge_index is (2, E)
    int N = in_sizes[0] / 128;  // x is (N, 128)
    int nTiles = (E + TILE_M - 1) / TILE_M;

    cudaFuncSetAttribute(edgepred_bf16_kernel,
                         cudaFuncAttributeMaxDynamicSharedMemorySize, SMEM_BYTES);

    edgepred_bf16_kernel<<<nTiles, THREADS, SMEM_BYTES>>>(
        x, ei, W1, b1, W2, b2, W3, b3, W4, b4, out, E, N);
}

// round 4
// speedup vs baseline: 3.1433x; 2.0714x over previous
#include <cuda_runtime.h>
#include <cuda_bf16.h>
#include <math.h>

#define TILE_M 128
#define THREADS 256
#define SAB 136   // bf16 elements per smem row (272B) -> conflict-free LDSM

// smem: sA[128*SAB bf16] | sB[128*SAB bf16] | sIdx[256 int] | sW4[128 float]
#define SMEM_BYTES (2*128*SAB*2 + 256*4 + 128*4)

__device__ __forceinline__ void ldsm_x4(unsigned* r, unsigned addr) {
    asm volatile("ldmatrix.sync.aligned.m8n8.x4.shared.b16 {%0,%1,%2,%3}, [%4];"
        : "=r"(r[0]), "=r"(r[1]), "=r"(r[2]), "=r"(r[3]) : "r"(addr));
}
__device__ __forceinline__ void ldsm_x4_t(unsigned* r, unsigned addr) {
    asm volatile("ldmatrix.sync.aligned.m8n8.x4.trans.shared.b16 {%0,%1,%2,%3}, [%4];"
        : "=r"(r[0]), "=r"(r[1]), "=r"(r[2]), "=r"(r[3]) : "r"(addr));
}
__device__ __forceinline__ void mma_bf16(float* c, const unsigned* a, const unsigned* b) {
    asm volatile(
        "mma.sync.aligned.m16n8k16.row.col.f32.bf16.bf16.f32 "
        "{%0,%1,%2,%3},{%4,%5,%6,%7},{%8,%9},{%0,%1,%2,%3};"
        : "+f"(c[0]), "+f"(c[1]), "+f"(c[2]), "+f"(c[3])
        : "r"(a[0]), "r"(a[1]), "r"(a[2]), "r"(a[3]), "r"(b[0]), "r"(b[1]));
}

__global__ void __launch_bounds__(THREADS, 2)
edgepred_bf16_kernel(
    const float* __restrict__ x,
    const int* __restrict__ ei,
    const float* __restrict__ W1, const float* __restrict__ b1,
    const float* __restrict__ W2, const float* __restrict__ b2,
    const float* __restrict__ W3, const float* __restrict__ b3,
    const float* __restrict__ W4, const float* __restrict__ b4,
    float* __restrict__ out, int E, int N)
{
    extern __shared__ char smem_raw[];
    __nv_bfloat16* sA = (__nv_bfloat16*)smem_raw;            // 128 x SAB
    __nv_bfloat16* sB = sA + 128 * SAB;                      // 128 x SAB
    int*   sIdx = (int*)(sB + 128 * SAB);                    // 256
    float* sW4  = (float*)(sIdx + 256);                      // 128

    const int tid    = threadIdx.x;
    const int lane   = tid & 31;
    const int wid    = tid >> 5;
    const int warp_m = wid >> 2;   // 0..1 -> rows [warp_m*64, +64)
    const int warp_n = wid & 3;    // 0..3 -> cols [warp_n*32, +32)
    const int qid    = lane >> 2;
    const int tig    = lane & 3;
    const long long tile0 = (long long)blockIdx.x * TILE_M;

    const unsigned sA_u = (unsigned)__cvta_generic_to_shared(sA);
    const unsigned sB_u = (unsigned)__cvta_generic_to_shared(sB);

    // ---- edge indices (src / dst), clamped ----
    {
        int half = (tid < 128) ? 0 : 1;
        int r    = tid & 127;
        long long e = tile0 + r;
        int idx = 0;
        if (e < E) idx = ei[(long long)half * E + e];
        if (idx < 0)  idx = 0;
        if (idx >= N) idx = N - 1;
        sIdx[half * 128 + r] = idx;
    }
    __syncthreads();

    // ---- coalesced row loaders: one warp loads one full 512B row per LDG ----
    // warp w handles rows w, w+8, ..., w+120 (16 rows). Lanes cover the row.
    auto store_row_bf16 = [&](__nv_bfloat16* dstRow, float4 v) {
        __nv_bfloat162 p0 = __floats2bfloat162_rn(v.x, v.y);
        __nv_bfloat162 p1 = __floats2bfloat162_rn(v.z, v.w);
        uint2 o;
        o.x = *(unsigned*)&p0;
        o.y = *(unsigned*)&p1;
        *(uint2*)(dstRow + lane * 4) = o;   // STS.64, conflict-free (2 phases)
    };
    auto load_act = [&](const int* idxs) {
        #pragma unroll
        for (int r = 0; r < 16; ++r) {
            int row = wid + r * 8;
            int node = idxs[row];                 // LDS broadcast
            float4 v = ((const float4*)(x + (long long)node * 128))[lane];
            store_row_bf16(sA + row * SAB, v);
        }
    };
    auto load_w = [&](const float* W) {
        #pragma unroll
        for (int r = 0; r < 16; ++r) {
            int row = wid + r * 8;
            float4 v = ((const float4*)(W + row * 128))[lane];
            store_row_bf16(sB + row * SAB, v);
        }
    };

    // ---- per-lane LDSM base addresses ----
    const int sub = lane >> 3;
    const int r8  = lane & 7;
    const unsigned aBase = sA_u + (((sub & 1) * 8 + r8) * SAB + (sub >> 1) * 8) * 2;
    const unsigned bBase = sB_u + (((sub & 1) * 8 + r8) * SAB + warp_n * 32 + (sub >> 1) * 8) * 2;

    float acc[4][4][4];
    auto zero_acc = [&]() {
        #pragma unroll
        for (int mt = 0; mt < 4; ++mt)
            #pragma unroll
            for (int nt = 0; nt < 4; ++nt)
                #pragma unroll
                for (int i = 0; i < 4; ++i) acc[mt][nt][i] = 0.f;
    };

    // 128x128x128 GEMM pass: sA @ sB -> acc
    auto run_mma = [&]() {
        #pragma unroll
        for (int kt = 0; kt < 8; ++kt) {
            unsigned a[4][4], b[2][4];
            #pragma unroll
            for (int mt = 0; mt < 4; ++mt)
                ldsm_x4(a[mt], aBase + (unsigned)((warp_m * 64 + mt * 16) * SAB + kt * 16) * 2);
            #pragma unroll
            for (int ntp = 0; ntp < 2; ++ntp)
                ldsm_x4_t(b[ntp], bBase + (unsigned)(kt * 16 * SAB + ntp * 16) * 2);
            #pragma unroll
            for (int mt = 0; mt < 4; ++mt)
                #pragma unroll
                for (int nt = 0; nt < 4; ++nt)
                    mma_bf16(acc[mt][nt], a[mt], &b[nt >> 1][(nt & 1) * 2]);
        }
    };

    // bias + relu -> bf16 back into sA
    auto epilogue = [&](const float* __restrict__ bias) {
        #pragma unroll
        for (int mt = 0; mt < 4; ++mt) {
            int row = warp_m * 64 + mt * 16 + qid;
            #pragma unroll
            for (int nt = 0; nt < 4; ++nt) {
                int col = warp_n * 32 + nt * 8 + 2 * tig;
                float bb0 = __ldg(&bias[col]);
                float bb1 = __ldg(&bias[col + 1]);
                float v0 = fmaxf(acc[mt][nt][0] + bb0, 0.f);
                float v1 = fmaxf(acc[mt][nt][1] + bb1, 0.f);
                float v2 = fmaxf(acc[mt][nt][2] + bb0, 0.f);
                float v3 = fmaxf(acc[mt][nt][3] + bb1, 0.f);
                *(__nv_bfloat162*)(sA + row * SAB + col)       = __floats2bfloat162_rn(v0, v1);
                *(__nv_bfloat162*)(sA + (row + 8) * SAB + col) = __floats2bfloat162_rn(v2, v3);
            }
        }
    };

    // ======== Layer 1, pass A: x_i @ W1[0:128] ========
    load_act(sIdx);
    load_w(W1);
    __syncthreads();
    zero_acc();
    run_mma();
    __syncthreads();

    // ======== Layer 1, pass B: + x_j @ W1[128:256] ========
    load_act(sIdx + 128);
    load_w(W1 + 128 * 128);
    __syncthreads();
    run_mma();
    __syncthreads();
    load_w(W2);          // issue LDGs first -> overlap with epilogue math
    epilogue(b1);
    __syncthreads();

    // ======== Layer 2 ========
    zero_acc();
    run_mma();
    __syncthreads();
    load_w(W3);
    epilogue(b2);
    __syncthreads();

    // ======== Layer 3 ========
    zero_acc();
    run_mma();
    __syncthreads();
    if (tid < 128) sW4[tid] = W4[tid];
    epilogue(b3);
    __syncthreads();

    // ======== Layer 4: dot(h3, W4) + sigmoid ========
    if (tid < 128) {
        long long e = tile0 + tid;
        if (e < E) {
            float z = __ldg(b4);
            const __nv_bfloat162* hr = (const __nv_bfloat162*)(sA + tid * SAB);
            #pragma unroll
            for (int j = 0; j < 64; ++j) {
                float2 h2 = __bfloat1622float2(hr[j]);
                z += h2.x * sW4[2 * j] + h2.y * sW4[2 * j + 1];
            }
            out[e] = 1.f / (1.f + expf(-z));
        }
    }
}

extern "C" void kernel_launch(void* const* d_in, const int* in_sizes, int n_in,
                              void* d_out, int out_size)
{
    const float* x  = (const float*)d_in[0];
    const int*   ei = (const int*)d_in[1];
    const float* W1 = (const float*)d_in[2];
    const float* b1 = (const float*)d_in[3];
    const float* W2 = (const float*)d_in[4];
    const float* b2 = (const float*)d_in[5];
    const float* W3 = (const float*)d_in[6];
    const float* b3 = (const float*)d_in[7];
    const float* W4 = (const float*)d_in[8];
    const float* b4 = (const float*)d_in[9];
    float* out = (float*)d_out;

    int E = in_sizes[1] / 2;    // edge_index is (2, E)
    int N = in_sizes[0] / 128;  // x is (N, 128)
    int nTiles = (E + TILE_M - 1) / TILE_M;

    cudaFuncSetAttribute(edgepred_bf16_kernel,
                         cudaFuncAttributeMaxDynamicSharedMemorySize, SMEM_BYTES);

    edgepred_bf16_kernel<<<nTiles, THREADS, SMEM_BYTES>>>(
        x, ei, W1, b1, W2, b2, W3, b3, W4, b4, out, E, N);
}